// round 10
// baseline (speedup 1.0000x reference)
#include <cuda_runtime.h>
#include <cstdint>

#define T_DIM 512
#define B_DIM 512
#define I_DIM 100
#define H_DIM 96
#define G_DIM 288   // 3*H

// Scratch for input projections: [dir][t][b][3H]  (604 MB, static device alloc — allowed)
__device__ float g_xp[2][T_DIM][B_DIM][G_DIM];

// ---------------------------------------------------------------------------
// packed f32x2 ops (Blackwell)
// ---------------------------------------------------------------------------
__device__ __forceinline__ float2 ffma2(float2 a, float2 b, float2 c) {
    float2 d;
    asm("fma.rn.f32x2 %0, %1, %2, %3;"
        : "=l"(*reinterpret_cast<unsigned long long*>(&d))
        : "l"(*reinterpret_cast<unsigned long long*>(&a)),
          "l"(*reinterpret_cast<unsigned long long*>(&b)),
          "l"(*reinterpret_cast<unsigned long long*>(&c)));
    return d;
}
__device__ __forceinline__ float2 fadd2(float2 a, float2 b) {
    float2 d;
    asm("add.rn.f32x2 %0, %1, %2;"
        : "=l"(*reinterpret_cast<unsigned long long*>(&d))
        : "l"(*reinterpret_cast<unsigned long long*>(&a)),
          "l"(*reinterpret_cast<unsigned long long*>(&b)));
    return d;
}

__device__ __forceinline__ float sigmoidf_fast(float x) {
    return __fdividef(1.0f, 1.0f + __expf(-x));
}
__device__ __forceinline__ float tanhf_fast(float x) {
    return 2.0f * __fdividef(1.0f, 1.0f + __expf(-2.0f * x)) - 1.0f;
}

// ---------------------------------------------------------------------------
// Kernel 1: input projection, register-blocked 4 cols x 8 rows per thread.
// grid (74, dir=2, ghalf=2), block 288, 2 CTAs/SM (85.2 KB smem).
// Thread = (gl in [0,36), rh in [0,8)): cols {gl,gl+36,gl+72,gl+108} (local),
// rows rh*8..+8 of a 64-row tile. Per k: 2 LDS.128 (x) + 4 LDS.32 (w) feed
// 16 ffma2 -> 12 load regs/k, unroll 4 fits the 113-reg budget.
// ---------------------------------------------------------------------------
#define PROJ_TM 64
#define GH 144
#define WS2_STRIDE 145
#define XS_STRIDE 68

extern __shared__ float proj_sm[];

__global__ void __launch_bounds__(288, 2)
proj_kernel(const float* __restrict__ x,
            const float* __restrict__ w_f, const float* __restrict__ b_f,
            const float* __restrict__ w_b, const float* __restrict__ b_b)
{
    float* Ws = proj_sm;                        // [100][145]
    float* Xs = proj_sm + I_DIM * WS2_STRIDE;   // [100][68]

    const int dir   = blockIdx.y;
    const int ghalf = blockIdx.z;
    const float* __restrict__ W    = dir ? w_b : w_f;
    const float* __restrict__ bias = dir ? b_b : b_f;
    const int tid = threadIdx.x;
    const int gl  = tid % 36;         // local column base
    const int rh  = tid / 36;         // row octet (0..7)

    // Load this CTA's 144 W columns transposed: Ws[k][gg] = W[ghalf*144+gg][k]
    for (int idx = tid; idx < GH * I_DIM; idx += 288) {
        int gg = idx / I_DIM;
        int k  = idx - gg * I_DIM;
        Ws[k * WS2_STRIDE + gg] = W[(size_t)(ghalf * GH + gg) * I_DIM + k];
    }
    float bg[4];
    #pragma unroll
    for (int cc = 0; cc < 4; cc++) bg[cc] = bias[ghalf * GH + gl + 36 * cc];

    float* __restrict__ xp_base = &g_xp[dir][0][0][0];

    const int ntiles = (T_DIM * B_DIM) / PROJ_TM;   // 4096
    for (int tile = blockIdx.x; tile < ntiles; tile += gridDim.x) {
        const size_t row0 = (size_t)tile * PROJ_TM;

        __syncthreads();   // prior tile's Xs reads done (also orders Ws on iter 0)
        for (int idx = tid; idx < PROJ_TM * I_DIM; idx += 288) {
            int r = idx / I_DIM;
            int k = idx - r * I_DIM;
            Xs[k * XS_STRIDE + r] = x[(row0 + r) * I_DIM + k];
        }
        __syncthreads();

        // acc[cc][p]: cols gl+36*cc, row pair (2p, 2p+1) of this octet
        float2 acc[4][4];
        #pragma unroll
        for (int cc = 0; cc < 4; cc++)
            #pragma unroll
            for (int p = 0; p < 4; p++) acc[cc][p] = make_float2(bg[cc], bg[cc]);

        #pragma unroll 4
        for (int k = 0; k < I_DIM; k++) {
            const float* xr = &Xs[k * XS_STRIDE + rh * 8];
            float4 xA = *reinterpret_cast<const float4*>(xr);
            float4 xB = *reinterpret_cast<const float4*>(xr + 4);
            float2 h01 = make_float2(xA.x, xA.y);
            float2 h23 = make_float2(xA.z, xA.w);
            float2 h45 = make_float2(xB.x, xB.y);
            float2 h67 = make_float2(xB.z, xB.w);
            #pragma unroll
            for (int cc = 0; cc < 4; cc++) {
                float w = Ws[k * WS2_STRIDE + gl + 36 * cc];
                float2 wp = make_float2(w, w);
                acc[cc][0] = ffma2(h01, wp, acc[cc][0]);
                acc[cc][1] = ffma2(h23, wp, acc[cc][1]);
                acc[cc][2] = ffma2(h45, wp, acc[cc][2]);
                acc[cc][3] = ffma2(h67, wp, acc[cc][3]);
            }
        }

        float* __restrict__ outp =
            xp_base + (row0 + rh * 8) * G_DIM + ghalf * GH + gl;
        #pragma unroll
        for (int cc = 0; cc < 4; cc++) {
            #pragma unroll
            for (int p = 0; p < 4; p++) {
                outp[(size_t)(2 * p)     * G_DIM + 36 * cc] = acc[cc][p].x;
                outp[(size_t)(2 * p + 1) * G_DIM + 36 * cc] = acc[cc][p].y;
            }
        }
    }
}

// ---------------------------------------------------------------------------
// Kernel 2: single-phase GRU scan. grid (64, 2), block 768 (24 warps).
// Thread = (j in [0,96), kq in [0,8)): owns gate triple {j,j+96,j+192} over
// k in {kq + 8i : i<12} (36 W regs), accumulates all 8 rows (12 f32x2).
// kq partners warp-local (tid = j*8+kq): 3-round butterfly all-reduce, then
// lane kq computes the gate for row kq entirely in registers. h double-
// buffered in smem -> ONE barrier per step. 6 warps/SMSP hide shfl/LDS tails.
// ---------------------------------------------------------------------------
#define R_PER_CTA 8
#define KPT 12   // k-values per thread

__global__ void __launch_bounds__(768, 1)
scan_kernel(const float* __restrict__ whh_f, const float* __restrict__ bhh_f,
            const float* __restrict__ whh_b, const float* __restrict__ bhh_b,
            float* __restrict__ out)
{
    __shared__ __align__(16) float h_s[2][H_DIM * R_PER_CTA];   // double-buffered [k][r]

    const int dir = blockIdx.y;
    const float* __restrict__ Whh = dir ? whh_b : whh_f;
    const float* __restrict__ bhh = dir ? bhh_b : bhh_f;
    const int tid = threadIdx.x;
    const int j   = tid >> 3;          // 0..95  (gate triple)
    const int kq  = tid & 7;           // 0..7   (k eighth; also owned row)
    const int b0  = blockIdx.x * R_PER_CTA;

    // W_hh columns j / j+96 / j+192 at k = kq + 8i  -> 36 registers
    float wr[KPT], wz[KPT], wn[KPT];
    #pragma unroll
    for (int i = 0; i < KPT; i++) {
        int k = kq + 8 * i;
        wr[i] = Whh[(size_t)j * H_DIM + k];
        wz[i] = Whh[(size_t)(j + 96) * H_DIM + k];
        wn[i] = Whh[(size_t)(j + 192) * H_DIM + k];
    }
    const float br = (kq == 0) ? bhh[j]       : 0.0f;   // bias counted once
    const float bz = (kq == 0) ? bhh[j + 96]  : 0.0f;
    const float bn = (kq == 0) ? bhh[j + 192] : 0.0f;

    // h0 = 0 (both buffers) + register-resident h_old (row kq)
    for (int i = tid; i < 2 * H_DIM * R_PER_CTA; i += 768)
        (&h_s[0][0])[i] = 0.0f;
    float hold = 0.0f;
    __syncthreads();

    const float* __restrict__ xp_dir = &g_xp[dir][0][0][0];

    for (int s = 0; s < T_DIM; s++) {
        const int t = dir ? (T_DIM - 1 - s) : s;

        // Prefetch x-projections for row kq (consumed post-matvec)
        const float* __restrict__ p0 =
            xp_dir + ((size_t)t * B_DIM + b0 + kq) * G_DIM + j;
        float xr = p0[0], xz = p0[96], xn = p0[192];

        // Partial matvec over k = kq+8i for all 8 rows, 3 gate columns
        const float* __restrict__ hb = h_s[s & 1];
        float2 ar0 = make_float2(br, br), ar1 = ar0, ar2 = ar0, ar3 = ar0;
        float2 az0 = make_float2(bz, bz), az1 = az0, az2 = az0, az3 = az0;
        float2 an0 = make_float2(bn, bn), an1 = an0, an2 = an0, an3 = an0;
        #pragma unroll
        for (int i = 0; i < KPT; i++) {
            int k = kq + 8 * i;
            float4 hA = *reinterpret_cast<const float4*>(&hb[k * 8]);
            float4 hB = *reinterpret_cast<const float4*>(&hb[k * 8 + 4]);
            float2 h01 = make_float2(hA.x, hA.y);
            float2 h23 = make_float2(hA.z, hA.w);
            float2 h45 = make_float2(hB.x, hB.y);
            float2 h67 = make_float2(hB.z, hB.w);
            float2 w2;
            w2 = make_float2(wr[i], wr[i]);
            ar0 = ffma2(h01, w2, ar0); ar1 = ffma2(h23, w2, ar1);
            ar2 = ffma2(h45, w2, ar2); ar3 = ffma2(h67, w2, ar3);
            w2 = make_float2(wz[i], wz[i]);
            az0 = ffma2(h01, w2, az0); az1 = ffma2(h23, w2, az1);
            az2 = ffma2(h45, w2, az2); az3 = ffma2(h67, w2, az3);
            w2 = make_float2(wn[i], wn[i]);
            an0 = ffma2(h01, w2, an0); an1 = ffma2(h23, w2, an1);
            an2 = ffma2(h45, w2, an2); an3 = ffma2(h67, w2, an3);
        }

        // Butterfly all-reduce over the 8 kq lanes (warp-local, 3 rounds)
        #define RED2(v, m)                                            \
            { float2 _o;                                              \
              _o.x = __shfl_xor_sync(0xFFFFFFFFu, (v).x, (m));        \
              _o.y = __shfl_xor_sync(0xFFFFFFFFu, (v).y, (m));        \
              (v) = fadd2((v), _o); }
        #define REDALL(m)                                             \
            RED2(ar0, m) RED2(ar1, m) RED2(ar2, m) RED2(ar3, m)       \
            RED2(az0, m) RED2(az1, m) RED2(az2, m) RED2(az3, m)       \
            RED2(an0, m) RED2(an1, m) RED2(an2, m) RED2(an3, m)
        REDALL(1)
        REDALL(2)
        REDALL(4)
        #undef REDALL
        #undef RED2

        // Lane kq takes row kq: pair = kq>>1, component = kq&1
        float2 ur0, ur1, vr2, uz0, uz1, vz2, un0, un1, vn2;
        ur0 = (kq & 2) ? ar1 : ar0;  ur1 = (kq & 2) ? ar3 : ar2;
        uz0 = (kq & 2) ? az1 : az0;  uz1 = (kq & 2) ? az3 : az2;
        un0 = (kq & 2) ? an1 : an0;  un1 = (kq & 2) ? an3 : an2;
        vr2 = (kq & 4) ? ur1 : ur0;
        vz2 = (kq & 4) ? uz1 : uz0;
        vn2 = (kq & 4) ? un1 : un0;
        float vr = (kq & 1) ? vr2.y : vr2.x;
        float vz = (kq & 1) ? vz2.y : vz2.x;
        float vn = (kq & 1) ? vn2.y : vn2.x;

        // Gate for row kq — entirely in registers
        float rg = sigmoidf_fast(xr + vr);
        float zg = sigmoidf_fast(xz + vz);
        float ng = tanhf_fast(xn + rg * vn);
        float hnew = ng + zg * (hold - ng);
        hold = hnew;

        // Write next-state buffer (parity s+1) + output
        h_s[(s + 1) & 1][j * 8 + kq] = hnew;   // == index tid: coalesced
        out[((size_t)t * B_DIM + b0 + kq) * (2 * H_DIM) + dir * H_DIM + j] = hnew;

        __syncthreads();   // buffer (s+1) complete; buffer s reads all done
    }
}

// ---------------------------------------------------------------------------
extern "C" void kernel_launch(void* const* d_in, const int* in_sizes, int n_in,
                              void* d_out, int out_size)
{
    const float* x      = (const float*)d_in[0];
    const float* w_ih_f = (const float*)d_in[1];
    const float* w_hh_f = (const float*)d_in[2];
    const float* b_ih_f = (const float*)d_in[3];
    const float* b_hh_f = (const float*)d_in[4];
    const float* w_ih_b = (const float*)d_in[5];
    const float* w_hh_b = (const float*)d_in[6];
    const float* b_ih_b = (const float*)d_in[7];
    const float* b_hh_b = (const float*)d_in[8];
    float* out = (float*)d_out;

    const int smem_proj = (I_DIM * WS2_STRIDE + I_DIM * XS_STRIDE) * sizeof(float); // 85.2 KB
    cudaFuncSetAttribute(proj_kernel, cudaFuncAttributeMaxDynamicSharedMemorySize, smem_proj);

    proj_kernel<<<dim3(74, 2, 2), 288, smem_proj>>>(x, w_ih_f, b_ih_f, w_ih_b, b_ih_b);
    scan_kernel<<<dim3(B_DIM / R_PER_CTA, 2), 768>>>(w_hh_f, b_hh_f, w_hh_b, b_hh_b, out);
}

// round 11
// speedup vs baseline: 1.3967x; 1.3967x over previous
#include <cuda_runtime.h>
#include <cstdint>

#define T_DIM 512
#define B_DIM 512
#define I_DIM 100
#define H_DIM 96
#define G_DIM 288   // 3*H

// Scratch for input projections: [dir][t][b][3H]  (604 MB, static device alloc — allowed)
__device__ float g_xp[2][T_DIM][B_DIM][G_DIM];

// ---------------------------------------------------------------------------
// packed f32x2 ops (Blackwell)
// ---------------------------------------------------------------------------
__device__ __forceinline__ float2 ffma2(float2 a, float2 b, float2 c) {
    float2 d;
    asm("fma.rn.f32x2 %0, %1, %2, %3;"
        : "=l"(*reinterpret_cast<unsigned long long*>(&d))
        : "l"(*reinterpret_cast<unsigned long long*>(&a)),
          "l"(*reinterpret_cast<unsigned long long*>(&b)),
          "l"(*reinterpret_cast<unsigned long long*>(&c)));
    return d;
}
__device__ __forceinline__ float2 fadd2(float2 a, float2 b) {
    float2 d;
    asm("add.rn.f32x2 %0, %1, %2;"
        : "=l"(*reinterpret_cast<unsigned long long*>(&d))
        : "l"(*reinterpret_cast<unsigned long long*>(&a)),
          "l"(*reinterpret_cast<unsigned long long*>(&b)));
    return d;
}

__device__ __forceinline__ float sigmoidf_fast(float x) {
    return __fdividef(1.0f, 1.0f + __expf(-x));
}
__device__ __forceinline__ float tanhf_fast(float x) {
    return 2.0f * __fdividef(1.0f, 1.0f + __expf(-2.0f * x)) - 1.0f;
}

// ---------------------------------------------------------------------------
// Kernel 1: input projection, register-blocked 4 cols x 8 rows per thread
// (unchanged from round 10). grid (74, 2, 2), block 288, 2 CTAs/SM.
// ---------------------------------------------------------------------------
#define PROJ_TM 64
#define GH 144
#define WS2_STRIDE 145
#define XS_STRIDE 68

extern __shared__ float proj_sm[];

__global__ void __launch_bounds__(288, 2)
proj_kernel(const float* __restrict__ x,
            const float* __restrict__ w_f, const float* __restrict__ b_f,
            const float* __restrict__ w_b, const float* __restrict__ b_b)
{
    float* Ws = proj_sm;                        // [100][145]
    float* Xs = proj_sm + I_DIM * WS2_STRIDE;   // [100][68]

    const int dir   = blockIdx.y;
    const int ghalf = blockIdx.z;
    const float* __restrict__ W    = dir ? w_b : w_f;
    const float* __restrict__ bias = dir ? b_b : b_f;
    const int tid = threadIdx.x;
    const int gl  = tid % 36;         // local column base
    const int rh  = tid / 36;         // row octet (0..7)

    for (int idx = tid; idx < GH * I_DIM; idx += 288) {
        int gg = idx / I_DIM;
        int k  = idx - gg * I_DIM;
        Ws[k * WS2_STRIDE + gg] = W[(size_t)(ghalf * GH + gg) * I_DIM + k];
    }
    float bg[4];
    #pragma unroll
    for (int cc = 0; cc < 4; cc++) bg[cc] = bias[ghalf * GH + gl + 36 * cc];

    float* __restrict__ xp_base = &g_xp[dir][0][0][0];

    const int ntiles = (T_DIM * B_DIM) / PROJ_TM;   // 4096
    for (int tile = blockIdx.x; tile < ntiles; tile += gridDim.x) {
        const size_t row0 = (size_t)tile * PROJ_TM;

        __syncthreads();
        for (int idx = tid; idx < PROJ_TM * I_DIM; idx += 288) {
            int r = idx / I_DIM;
            int k = idx - r * I_DIM;
            Xs[k * XS_STRIDE + r] = x[(row0 + r) * I_DIM + k];
        }
        __syncthreads();

        float2 acc[4][4];
        #pragma unroll
        for (int cc = 0; cc < 4; cc++)
            #pragma unroll
            for (int p = 0; p < 4; p++) acc[cc][p] = make_float2(bg[cc], bg[cc]);

        #pragma unroll 4
        for (int k = 0; k < I_DIM; k++) {
            const float* xr = &Xs[k * XS_STRIDE + rh * 8];
            float4 xA = *reinterpret_cast<const float4*>(xr);
            float4 xB = *reinterpret_cast<const float4*>(xr + 4);
            float2 h01 = make_float2(xA.x, xA.y);
            float2 h23 = make_float2(xA.z, xA.w);
            float2 h45 = make_float2(xB.x, xB.y);
            float2 h67 = make_float2(xB.z, xB.w);
            #pragma unroll
            for (int cc = 0; cc < 4; cc++) {
                float w = Ws[k * WS2_STRIDE + gl + 36 * cc];
                float2 wp = make_float2(w, w);
                acc[cc][0] = ffma2(h01, wp, acc[cc][0]);
                acc[cc][1] = ffma2(h23, wp, acc[cc][1]);
                acc[cc][2] = ffma2(h45, wp, acc[cc][2]);
                acc[cc][3] = ffma2(h67, wp, acc[cc][3]);
            }
        }

        float* __restrict__ outp =
            xp_base + (row0 + rh * 8) * G_DIM + ghalf * GH + gl;
        #pragma unroll
        for (int cc = 0; cc < 4; cc++) {
            #pragma unroll
            for (int p = 0; p < 4; p++) {
                outp[(size_t)(2 * p)     * G_DIM + 36 * cc] = acc[cc][p].x;
                outp[(size_t)(2 * p + 1) * G_DIM + 36 * cc] = acc[cc][p].y;
            }
        }
    }
}

// ---------------------------------------------------------------------------
// Kernel 2: single-phase GRU scan, 384 threads (round-9 shape) with a
// VALUE-SPLITTING tree reduce instead of the all-reduce.
// Thread = (j in [0,96), kq in [0,4)): gate triple {j,j+96,j+192} over
// k in {kq + 4i : i<24} (72 W regs), accumulates all 8 rows (12 f32x2).
// Reduce: round 1 (mask 2) keep own 4-row block, round 2 (mask 1) keep own
// row pair -> 18 SHFL + 9 FADD2 per thread (vs 48+24), no final selects.
// Lane kq then computes gates for rows {2kq, 2kq+1} in registers.
// h double-buffered in smem -> ONE barrier per step.
// ---------------------------------------------------------------------------
#define R_PER_CTA 8
#define KPT 24   // k-values per thread

__global__ void __launch_bounds__(384, 1)
scan_kernel(const float* __restrict__ whh_f, const float* __restrict__ bhh_f,
            const float* __restrict__ whh_b, const float* __restrict__ bhh_b,
            float* __restrict__ out)
{
    __shared__ __align__(16) float h_s[2][H_DIM * R_PER_CTA];   // double-buffered [k][r]

    const int dir = blockIdx.y;
    const float* __restrict__ Whh = dir ? whh_b : whh_f;
    const float* __restrict__ bhh = dir ? bhh_b : bhh_f;
    const int tid = threadIdx.x;
    const int j   = tid >> 2;          // 0..95  (gate triple)
    const int kq  = tid & 3;           // 0..3   (k quarter, warp-local lanes)
    const int b0  = blockIdx.x * R_PER_CTA;
    const int r0  = 2 * kq;            // rows owned in the gate phase
    const bool hi_blk  = (kq & 2) != 0;   // owns rows 4-7 after round 1
    const bool hi_pair = (kq & 1) != 0;   // owns upper pair after round 2

    // W_hh columns j / j+96 / j+192 at k = kq + 4i  -> 72 registers
    float wr[KPT], wz[KPT], wn[KPT];
    #pragma unroll
    for (int i = 0; i < KPT; i++) {
        int k = kq + 4 * i;
        wr[i] = Whh[(size_t)j * H_DIM + k];
        wz[i] = Whh[(size_t)(j + 96) * H_DIM + k];
        wn[i] = Whh[(size_t)(j + 192) * H_DIM + k];
    }
    const float br = (kq == 0) ? bhh[j]       : 0.0f;   // bias counted once
    const float bz = (kq == 0) ? bhh[j + 96]  : 0.0f;
    const float bn = (kq == 0) ? bhh[j + 192] : 0.0f;

    // h0 = 0 (both buffers) + register-resident h_old
    for (int i = tid; i < 2 * H_DIM * R_PER_CTA; i += 384)
        (&h_s[0][0])[i] = 0.0f;
    float hold0 = 0.0f, hold1 = 0.0f;
    __syncthreads();

    const float* __restrict__ xp_dir = &g_xp[dir][0][0][0];

    for (int s = 0; s < T_DIM; s++) {
        const int t = dir ? (T_DIM - 1 - s) : s;

        // Prefetch x-projections for this thread's 2 rows (consumed post-matvec)
        const float* __restrict__ p0 =
            xp_dir + ((size_t)t * B_DIM + b0 + r0) * G_DIM + j;
        const float* __restrict__ p1 = p0 + G_DIM;
        float xr0 = p0[0], xz0 = p0[96], xn0 = p0[192];
        float xr1 = p1[0], xz1 = p1[96], xn1 = p1[192];

        // Partial matvec over k = kq+4i for all 8 rows, 3 gate columns
        const float* __restrict__ hb = h_s[s & 1];
        float2 ar0 = make_float2(br, br), ar1 = ar0, ar2 = ar0, ar3 = ar0;
        float2 az0 = make_float2(bz, bz), az1 = az0, az2 = az0, az3 = az0;
        float2 an0 = make_float2(bn, bn), an1 = an0, an2 = an0, an3 = an0;
        #pragma unroll
        for (int i = 0; i < KPT; i++) {
            int k = kq + 4 * i;
            float4 hA = *reinterpret_cast<const float4*>(&hb[k * 8]);
            float4 hB = *reinterpret_cast<const float4*>(&hb[k * 8 + 4]);
            float2 h01 = make_float2(hA.x, hA.y);
            float2 h23 = make_float2(hA.z, hA.w);
            float2 h45 = make_float2(hB.x, hB.y);
            float2 h67 = make_float2(hB.z, hB.w);
            float2 w2;
            w2 = make_float2(wr[i], wr[i]);
            ar0 = ffma2(h01, w2, ar0); ar1 = ffma2(h23, w2, ar1);
            ar2 = ffma2(h45, w2, ar2); ar3 = ffma2(h67, w2, ar3);
            w2 = make_float2(wz[i], wz[i]);
            az0 = ffma2(h01, w2, az0); az1 = ffma2(h23, w2, az1);
            az2 = ffma2(h45, w2, az2); az3 = ffma2(h67, w2, az3);
            w2 = make_float2(wn[i], wn[i]);
            an0 = ffma2(h01, w2, an0); an1 = ffma2(h23, w2, an1);
            an2 = ffma2(h45, w2, an2); an3 = ffma2(h67, w2, an3);
        }

        // Value-splitting tree reduce over the 4 kq lanes (warp-local).
        // XSWAP(v, mask): exchange f32x2 with partner, returning received.
        #define XSWAP(v, m, dst)                                        \
            { (dst).x = __shfl_xor_sync(0xFFFFFFFFu, (v).x, (m));       \
              (dst).y = __shfl_xor_sync(0xFFFFFFFFu, (v).y, (m)); }
        // Round 1 (mask 2): keep own 4-row block (lo: accs *0,*1; hi: *2,*3)
        float2 rA, rB, A0, A1, Z0, Z1, N0, N1, sA, sB;
        sA = hi_blk ? ar0 : ar2;  XSWAP(sA, 2, rA);
        A0 = fadd2(hi_blk ? ar2 : ar0, rA);
        sB = hi_blk ? ar1 : ar3;  XSWAP(sB, 2, rB);
        A1 = fadd2(hi_blk ? ar3 : ar1, rB);
        sA = hi_blk ? az0 : az2;  XSWAP(sA, 2, rA);
        Z0 = fadd2(hi_blk ? az2 : az0, rA);
        sB = hi_blk ? az1 : az3;  XSWAP(sB, 2, rB);
        Z1 = fadd2(hi_blk ? az3 : az1, rB);
        sA = hi_blk ? an0 : an2;  XSWAP(sA, 2, rA);
        N0 = fadd2(hi_blk ? an2 : an0, rA);
        sB = hi_blk ? an1 : an3;  XSWAP(sB, 2, rB);
        N1 = fadd2(hi_blk ? an3 : an1, rB);
        // Round 2 (mask 1): keep own row pair (lo pair: A0; hi pair: A1)
        float2 vr, vz, vn, sC, rC;
        sC = hi_pair ? A0 : A1;  XSWAP(sC, 1, rC);
        vr = fadd2(hi_pair ? A1 : A0, rC);
        sC = hi_pair ? Z0 : Z1;  XSWAP(sC, 1, rC);
        vz = fadd2(hi_pair ? Z1 : Z0, rC);
        sC = hi_pair ? N0 : N1;  XSWAP(sC, 1, rC);
        vn = fadd2(hi_pair ? N1 : N0, rC);
        #undef XSWAP

        // Gates for rows r0, r0+1 — entirely in registers
        float rg0 = sigmoidf_fast(xr0 + vr.x);
        float zg0 = sigmoidf_fast(xz0 + vz.x);
        float ng0 = tanhf_fast(xn0 + rg0 * vn.x);
        float hn0 = ng0 + zg0 * (hold0 - ng0);
        float rg1 = sigmoidf_fast(xr1 + vr.y);
        float zg1 = sigmoidf_fast(xz1 + vz.y);
        float ng1 = tanhf_fast(xn1 + rg1 * vn.y);
        float hn1 = ng1 + zg1 * (hold1 - ng1);
        hold0 = hn0;
        hold1 = hn1;

        // Write next-state buffer (parity s+1) + output
        float* __restrict__ hw = h_s[(s + 1) & 1];
        *reinterpret_cast<float2*>(&hw[j * 8 + r0]) = make_float2(hn0, hn1);

        float* __restrict__ op =
            out + ((size_t)t * B_DIM + b0 + r0) * (2 * H_DIM) + dir * H_DIM + j;
        op[0]         = hn0;
        op[2 * H_DIM] = hn1;

        __syncthreads();   // buffer (s+1) complete; buffer s reads all done
    }
}

// ---------------------------------------------------------------------------
extern "C" void kernel_launch(void* const* d_in, const int* in_sizes, int n_in,
                              void* d_out, int out_size)
{
    const float* x      = (const float*)d_in[0];
    const float* w_ih_f = (const float*)d_in[1];
    const float* w_hh_f = (const float*)d_in[2];
    const float* b_ih_f = (const float*)d_in[3];
    const float* b_hh_f = (const float*)d_in[4];
    const float* w_ih_b = (const float*)d_in[5];
    const float* w_hh_b = (const float*)d_in[6];
    const float* b_ih_b = (const float*)d_in[7];
    const float* b_hh_b = (const float*)d_in[8];
    float* out = (float*)d_out;

    const int smem_proj = (I_DIM * WS2_STRIDE + I_DIM * XS_STRIDE) * sizeof(float); // 85.2 KB
    cudaFuncSetAttribute(proj_kernel, cudaFuncAttributeMaxDynamicSharedMemorySize, smem_proj);

    proj_kernel<<<dim3(74, 2, 2), 288, smem_proj>>>(x, w_ih_f, b_ih_f, w_ih_b, b_ih_b);
    scan_kernel<<<dim3(B_DIM / R_PER_CTA, 2), 384>>>(w_hh_f, b_hh_f, w_hh_b, b_hh_b, out);
}